// round 7
// baseline (speedup 1.0000x reference)
#include <cuda_runtime.h>
#include <cuda_bf16.h>

// GatheringLoss — R7: R6 with NON-VOLATILE mma asm so ptxas may interleave the
// 16 independent accumulator chains and hide LDSM latency. (volatile asm pinned
// the whole mainloop into program order -> 3.3% issue.)
//   approx score = q_hi*k_hi + q_hi*k_lo + q_lo*k_hi  (fp32 accum, HMMA)
//   per-row approx top-2 -> exact fp32 rescore -> argmax (first-max ties)
// out = [kg (65536) | vg (65536)]

#define T_TOTAL 65536
#define M_KEYS  1024
#define C_DIM   128
#define BM      128
#define THREADS 256
#define SAB     272

#define OFF_A_HI 0
#define OFF_A_LO 34816
#define OFF_B(buf) (69632 + (buf) * 69632)
#define OFF_B_LO 34816
#define SM_TOTAL 208896

__device__ __nv_bfloat16 g_keys_hi[M_KEYS * C_DIM];
__device__ __nv_bfloat16 g_keys_lo[M_KEYS * C_DIM];

__device__ __forceinline__ unsigned smem_u32(const void* p) {
    unsigned a;
    asm("{ .reg .u64 t; cvta.to.shared.u64 t, %1; cvt.u32.u64 %0, t; }" : "=r"(a) : "l"(p));
    return a;
}

// ldmatrix: stays volatile (reads smem produced by other threads across barriers)
#define LDSM_X4(r0, r1, r2, r3, a)                                             \
    asm volatile("ldmatrix.sync.aligned.m8n8.x4.shared.b16 {%0,%1,%2,%3}, [%4];" \
                 : "=r"(r0), "=r"(r1), "=r"(r2), "=r"(r3) : "r"(a))

// mma: NON-volatile — pure register dataflow, scheduler may reorder/interleave
__device__ __forceinline__ void mma_bf16(float* d, const unsigned* a,
                                         unsigned b0, unsigned b1) {
    asm("mma.sync.aligned.m16n8k16.row.col.f32.bf16.bf16.f32 "
        "{%0,%1,%2,%3}, {%4,%5,%6,%7}, {%8,%9}, {%0,%1,%2,%3};"
        : "+f"(d[0]), "+f"(d[1]), "+f"(d[2]), "+f"(d[3])
        : "r"(a[0]), "r"(a[1]), "r"(a[2]), "r"(a[3]), "r"(b0), "r"(b1));
}

#define CP16(dst, src) \
    asm volatile("cp.async.cg.shared.global [%0], [%1], 16;" :: "r"(dst), "l"(src))
#define CP_COMMIT() asm volatile("cp.async.commit_group;" ::: "memory")
#define CP_WAIT1()  asm volatile("cp.async.wait_group 1;"  ::: "memory")
#define CP_WAIT0()  asm volatile("cp.async.wait_group 0;"  ::: "memory")

#define UPD(s1, i1, s2, i2, v, n)                          \
    do { if ((v) > (s1)) { s2 = s1; i2 = i1; s1 = (v); i1 = (n); } \
         else if ((v) > (s2)) { s2 = (v); i2 = (n); } } while (0)

__device__ __forceinline__ void merge2(float& s1, int& i1, float& s2, int& i2,
                                       float t1, int j1, float t2, int j2) {
    if (t1 > s1 || (t1 == s1 && j1 < i1)) {
        float ns2; int ni2;
        if (s1 > t2 || (s1 == t2 && i1 < j2)) { ns2 = s1; ni2 = i1; }
        else                                  { ns2 = t2; ni2 = j2; }
        s1 = t1; i1 = j1; s2 = ns2; i2 = ni2;
    } else if (t1 > s2 || (t1 == s2 && j1 < i2)) {
        s2 = t1; i2 = j1;
    }
}

__global__ void prep_keys_kernel(const float* __restrict__ keys) {
    int i = blockIdx.x * blockDim.x + threadIdx.x;
    if (i < M_KEYS * C_DIM) {
        float v = keys[i];
        __nv_bfloat16 h = __float2bfloat16(v);
        g_keys_hi[i] = h;
        g_keys_lo[i] = __float2bfloat16(v - __bfloat162float(h));
    }
}

__global__ __launch_bounds__(THREADS, 1)
void gathering_loss_kernel(const float* __restrict__ q,
                           const float* __restrict__ r,
                           const float* __restrict__ keys,
                           const float* __restrict__ values,
                           float* __restrict__ out)
{
    extern __shared__ char smem[];
    const unsigned sb = smem_u32(smem);
    const int tid  = threadIdx.x;
    const int lane = tid & 31;
    const int wid  = tid >> 5;
    const int row0 = blockIdx.x * BM;

    // ---- A tiles: q rows -> bf16 hi/lo in smem [m][k] ----
    {
        const float4* q4 = (const float4*)(q + (size_t)row0 * C_DIM);
        #pragma unroll
        for (int it = 0; it < (BM * C_DIM / 4) / THREADS; ++it) {
            int i = tid + it * THREADS;
            int m  = i >> 5;
            int k4 = (i & 31) << 2;
            float4 v = q4[i];
            __nv_bfloat16 hx = __float2bfloat16(v.x), hy = __float2bfloat16(v.y);
            __nv_bfloat16 hz = __float2bfloat16(v.z), hw = __float2bfloat16(v.w);
            __nv_bfloat162 h01; h01.x = hx; h01.y = hy;
            __nv_bfloat162 h23; h23.x = hz; h23.y = hw;
            __nv_bfloat162 l01, l23;
            l01.x = __float2bfloat16(v.x - __bfloat162float(hx));
            l01.y = __float2bfloat16(v.y - __bfloat162float(hy));
            l23.x = __float2bfloat16(v.z - __bfloat162float(hz));
            l23.y = __float2bfloat16(v.w - __bfloat162float(hw));
            char* p = smem + m * SAB + k4 * 2;
            *(__nv_bfloat162*)(p + OFF_A_HI)     = h01;
            *(__nv_bfloat162*)(p + OFF_A_HI + 4) = h23;
            *(__nv_bfloat162*)(p + OFF_A_LO)     = l01;
            *(__nv_bfloat162*)(p + OFF_A_LO + 4) = l23;
        }
    }

    auto load_b = [&](int chunk, int buf) {
        const char* srch = (const char*)(g_keys_hi + (size_t)chunk * 128 * C_DIM);
        const char* srcl = (const char*)(g_keys_lo + (size_t)chunk * 128 * C_DIM);
        unsigned dsth = sb + OFF_B(buf);
        unsigned dstl = dsth + OFF_B_LO;
        #pragma unroll
        for (int it = 0; it < 8; ++it) {
            int s  = tid + it * THREADS;
            int n  = s >> 4;
            int ks = s & 15;
            CP16(dsth + n * SAB + ks * 16, srch + n * 256 + ks * 16);
            CP16(dstl + n * SAB + ks * 16, srcl + n * 256 + ks * 16);
        }
    };
    load_b(0, 0);
    CP_COMMIT();
    __syncthreads();

    const int amat = lane >> 3;
    const unsigned apart = sb + (unsigned)(wid * 16 + (lane & 7) + ((amat & 1) << 3)) * SAB
                         + ((amat >> 1) << 4);
    const int bmat = lane >> 3;
    const unsigned bpart = (bmat >= 2 ? OFF_B_LO : 0)
                         + (unsigned)(lane & 7) * SAB + ((bmat & 1) << 4);

    float s1a = -3.402823466e38f, s2a = -3.402823466e38f;
    float s1b = -3.402823466e38f, s2b = -3.402823466e38f;
    int i1a = 0, i2a = 0, i1b = 0, i2b = 0;

    #pragma unroll 1
    for (int c = 0; c < 8; ++c) {
        if (c < 7) { load_b(c + 1, (c + 1) & 1); CP_COMMIT(); CP_WAIT1(); }
        else       { CP_WAIT0(); }
        __syncthreads();

        const unsigned bbuf = sb + OFF_B(c & 1) + bpart;

        float acc[16][4];
        #pragma unroll
        for (int nt = 0; nt < 16; ++nt)
            #pragma unroll
            for (int x = 0; x < 4; ++x) acc[nt][x] = 0.f;

        #pragma unroll
        for (int ks = 0; ks < 8; ++ks) {
            unsigned ahi[4], alo[4];
            LDSM_X4(ahi[0], ahi[1], ahi[2], ahi[3], apart + OFF_A_HI + ks * 32);
            LDSM_X4(alo[0], alo[1], alo[2], alo[3], apart + OFF_A_LO + ks * 32);
            #pragma unroll
            for (int nt = 0; nt < 16; ++nt) {
                unsigned b0, b1, b2, b3;
                LDSM_X4(b0, b1, b2, b3, bbuf + (unsigned)(nt * 8) * SAB + ks * 32);
                mma_bf16(acc[nt], ahi, b0, b1);   // hi*hi
                mma_bf16(acc[nt], alo, b0, b1);   // lo*hi
                mma_bf16(acc[nt], ahi, b2, b3);   // hi*lo
            }
        }

        const int colbase = c * 128 + (lane & 3) * 2;
        #pragma unroll
        for (int nt = 0; nt < 16; ++nt) {
            int nb = colbase + nt * 8;
            UPD(s1a, i1a, s2a, i2a, acc[nt][0], nb);
            UPD(s1a, i1a, s2a, i2a, acc[nt][1], nb + 1);
            UPD(s1b, i1b, s2b, i2b, acc[nt][2], nb);
            UPD(s1b, i1b, s2b, i2b, acc[nt][3], nb + 1);
        }
        __syncthreads();
    }

    // ---- merge top-2 across quad lanes ----
    #pragma unroll
    for (int off = 1; off <= 2; off <<= 1) {
        float t1 = __shfl_xor_sync(0xffffffffu, s1a, off);
        int   j1 = __shfl_xor_sync(0xffffffffu, i1a, off);
        float t2 = __shfl_xor_sync(0xffffffffu, s2a, off);
        int   j2 = __shfl_xor_sync(0xffffffffu, i2a, off);
        merge2(s1a, i1a, s2a, i2a, t1, j1, t2, j2);
        t1 = __shfl_xor_sync(0xffffffffu, s1b, off);
        j1 = __shfl_xor_sync(0xffffffffu, i1b, off);
        t2 = __shfl_xor_sync(0xffffffffu, s2b, off);
        j2 = __shfl_xor_sync(0xffffffffu, i2b, off);
        merge2(s1b, i1b, s2b, i2b, t1, j1, t2, j2);
    }

    int* idx1 = (int*)smem;
    int* idx2 = idx1 + BM;
    if ((lane & 3) == 0) {
        int rw = wid * 16 + (lane >> 2);
        idx1[rw]     = i1a;  idx2[rw]     = i2a;
        idx1[rw + 8] = i1b;  idx2[rw + 8] = i2b;
    }
    __syncthreads();

    // ---- epilogue: exact fp32 rescore + losses (2 threads/row) ----
    {
        int row  = tid >> 1;
        int half = tid & 1;
        int grow = row0 + row;
        int c1 = idx1[row], c2 = idx2[row];
        const float4* qp = (const float4*)(q    + (size_t)grow * C_DIM + half * 64);
        const float4* ka = (const float4*)(keys + (size_t)c1   * C_DIM + half * 64);
        const float4* kb = (const float4*)(keys + (size_t)c2   * C_DIM + half * 64);
        float sa = 0.f, sc = 0.f;
        #pragma unroll
        for (int c = 0; c < 16; ++c) {
            float4 a = qp[c], x = ka[c], y = kb[c];
            sa = fmaf(a.x, x.x, sa); sa = fmaf(a.y, x.y, sa);
            sa = fmaf(a.z, x.z, sa); sa = fmaf(a.w, x.w, sa);
            sc = fmaf(a.x, y.x, sc); sc = fmaf(a.y, y.y, sc);
            sc = fmaf(a.z, y.z, sc); sc = fmaf(a.w, y.w, sc);
        }
        sa += __shfl_xor_sync(0xffffffffu, sa, 1);
        sc += __shfl_xor_sync(0xffffffffu, sc, 1);
        int kidx = (sc > sa || (sc == sa && c2 < c1)) ? c2 : c1;

        const float4* kp = (const float4*)(keys   + (size_t)kidx * C_DIM + half * 64);
        const float4* rp = (const float4*)(r      + (size_t)grow * C_DIM + half * 64);
        const float4* vp = (const float4*)(values + (size_t)kidx * C_DIM + half * 64);
        float sk = 0.f, sv = 0.f;
        #pragma unroll
        for (int c = 0; c < 16; ++c) {
            float4 a = qp[c], b = kp[c];
            float d;
            d = a.x - b.x; sk = fmaf(d, d, sk);
            d = a.y - b.y; sk = fmaf(d, d, sk);
            d = a.z - b.z; sk = fmaf(d, d, sk);
            d = a.w - b.w; sk = fmaf(d, d, sk);
            float4 e = rp[c], f = vp[c];
            d = e.x - f.x; sv = fmaf(d, d, sv);
            d = e.y - f.y; sv = fmaf(d, d, sv);
            d = e.z - f.z; sv = fmaf(d, d, sv);
            d = e.w - f.w; sv = fmaf(d, d, sv);
        }
        sk += __shfl_xor_sync(0xffffffffu, sk, 1);
        sv += __shfl_xor_sync(0xffffffffu, sv, 1);
        if (half == 0) out[grow]           = sk;
        else           out[T_TOTAL + grow] = sv;
    }
}

extern "C" void kernel_launch(void* const* d_in, const int* in_sizes, int n_in,
                              void* d_out, int out_size)
{
    const float* q      = (const float*)d_in[0];
    const float* r      = (const float*)d_in[1];
    const float* keys   = (const float*)d_in[2];
    const float* values = (const float*)d_in[3];
    float* out = (float*)d_out;

    prep_keys_kernel<<<(M_KEYS * C_DIM + 255) / 256, 256>>>(keys);

    cudaFuncSetAttribute(gathering_loss_kernel,
                         cudaFuncAttributeMaxDynamicSharedMemorySize, SM_TOTAL);
    gathering_loss_kernel<<<T_TOTAL / BM, THREADS, SM_TOTAL>>>(q, r, keys, values, out);
}

// round 8
// speedup vs baseline: 1.7276x; 1.7276x over previous
#include <cuda_runtime.h>
#include <cuda_fp16.h>

// GatheringLoss — R8: single-pass fp16 HMMA scoring (3x less MMA work than the
// bf16-split), 512 threads / 16 warps for 2x warp parallelism, per-thread
// approx top-2 -> 4 candidates/row -> exact fp32 rescore -> losses.
// out = [kg (65536) | vg (65536)]

#define T_TOTAL 65536
#define M_KEYS  1024
#define C_DIM   128
#define BM      128
#define THREADS 512
#define SAB     272                 // smem row stride (bytes)

#define OFF_A    0                  // 128 rows * 272B = 34816
#define OFF_B(buf) (34816 + (buf) * 34816)
#define SM_TOTAL  104448

__device__ __half g_keys_h[M_KEYS * C_DIM];

__device__ __forceinline__ unsigned smem_u32(const void* p) {
    unsigned a;
    asm("{ .reg .u64 t; cvta.to.shared.u64 t, %1; cvt.u32.u64 %0, t; }" : "=r"(a) : "l"(p));
    return a;
}

#define LDSM_X4(r0, r1, r2, r3, a)                                             \
    asm volatile("ldmatrix.sync.aligned.m8n8.x4.shared.b16 {%0,%1,%2,%3}, [%4];" \
                 : "=r"(r0), "=r"(r1), "=r"(r2), "=r"(r3) : "r"(a))

__device__ __forceinline__ void mma_f16(float* d, const unsigned* a,
                                        unsigned b0, unsigned b1) {
    asm("mma.sync.aligned.m16n8k16.row.col.f32.f16.f16.f32 "
        "{%0,%1,%2,%3}, {%4,%5,%6,%7}, {%8,%9}, {%0,%1,%2,%3};"
        : "+f"(d[0]), "+f"(d[1]), "+f"(d[2]), "+f"(d[3])
        : "r"(a[0]), "r"(a[1]), "r"(a[2]), "r"(a[3]), "r"(b0), "r"(b1));
}

#define CP16(dst, src) \
    asm volatile("cp.async.cg.shared.global [%0], [%1], 16;" :: "r"(dst), "l"(src))
#define CP_COMMIT() asm volatile("cp.async.commit_group;" ::: "memory")
#define CP_WAIT1()  asm volatile("cp.async.wait_group 1;"  ::: "memory")
#define CP_WAIT0()  asm volatile("cp.async.wait_group 0;"  ::: "memory")

#define UPD(s1, i1, s2, i2, v, n)                          \
    do { if ((v) > (s1)) { s2 = s1; i2 = i1; s1 = (v); i1 = (n); } \
         else if ((v) > (s2)) { s2 = (v); i2 = (n); } } while (0)

__device__ __forceinline__ void merge2(float& s1, int& i1, float& s2, int& i2,
                                       float t1, int j1, float t2, int j2) {
    if (t1 > s1 || (t1 == s1 && j1 < i1)) {
        float ns2; int ni2;
        if (s1 > t2 || (s1 == t2 && i1 < j2)) { ns2 = s1; ni2 = i1; }
        else                                  { ns2 = t2; ni2 = j2; }
        s1 = t1; i1 = j1; s2 = ns2; i2 = ni2;
    } else if (t1 > s2 || (t1 == s2 && j1 < i2)) {
        s2 = t1; i2 = j1;
    }
}

__global__ void prep_keys_kernel(const float* __restrict__ keys) {
    int i = blockIdx.x * blockDim.x + threadIdx.x;
    if (i < M_KEYS * C_DIM) g_keys_h[i] = __float2half_rn(keys[i]);
}

__global__ __launch_bounds__(THREADS, 1)
void gathering_loss_kernel(const float* __restrict__ q,
                           const float* __restrict__ r,
                           const float* __restrict__ keys,
                           const float* __restrict__ values,
                           float* __restrict__ out)
{
    extern __shared__ char smem[];
    const unsigned sb = smem_u32(smem);
    const int tid   = threadIdx.x;
    const int lane  = tid & 31;
    const int wid   = tid >> 5;          // 0..15
    const int rowg  = (wid & 7) * 16;    // warp's 16-row group
    const int half  = wid >> 3;          // warp's 64-key half of each chunk
    const int row0  = blockIdx.x * BM;

    // ---- A tile: q rows -> fp16 smem [m][k], stride 272B ----
    {
        const float4* q4 = (const float4*)(q + (size_t)row0 * C_DIM);
        #pragma unroll
        for (int it = 0; it < (BM * C_DIM / 4) / THREADS; ++it) {
            int i = tid + it * THREADS;
            int m  = i >> 5;
            int k4 = (i & 31) << 2;
            float4 v = q4[i];
            __half2 h01 = __floats2half2_rn(v.x, v.y);
            __half2 h23 = __floats2half2_rn(v.z, v.w);
            char* p = smem + OFF_A + m * SAB + k4 * 2;
            *(__half2*)(p)     = h01;
            *(__half2*)(p + 4) = h23;
        }
    }

    auto load_b = [&](int chunk, int buf) {
        const char* src = (const char*)(g_keys_h + (size_t)chunk * 128 * C_DIM);
        unsigned dst = sb + OFF_B(buf);
        #pragma unroll
        for (int it = 0; it < 4; ++it) {
            int s  = tid + it * THREADS;       // 2048 16B segments
            int n  = s >> 4;
            int ks = s & 15;
            CP16(dst + n * SAB + ks * 16, src + n * 256 + ks * 16);
        }
    };
    load_b(0, 0);
    CP_COMMIT();
    __syncthreads();

    // ---- persistent A fragments (32 regs) ----
    unsigned ahi[8][4];
    {
        int amat = lane >> 3;
        unsigned apart = sb + OFF_A
                       + (unsigned)(rowg + (lane & 7) + ((amat & 1) << 3)) * SAB
                       + ((amat >> 1) << 4);
        #pragma unroll
        for (int ks = 0; ks < 8; ++ks)
            LDSM_X4(ahi[ks][0], ahi[ks][1], ahi[ks][2], ahi[ks][3], apart + ks * 32);
    }

    // B ldmatrix: x4 loads TWO adjacent n8 tiles (mats 0,1 -> nt even; 2,3 -> nt odd)
    const int bmat = lane >> 3;
    const unsigned bpart = (unsigned)((lane & 7) + ((bmat >> 1) << 3)) * SAB
                         + ((bmat & 1) << 4)
                         + (unsigned)(half * 64) * SAB;

    float s1a = -3.402823466e38f, s2a = -3.402823466e38f;
    float s1b = -3.402823466e38f, s2b = -3.402823466e38f;
    int i1a = 0, i2a = 0, i1b = 0, i2b = 0;

    #pragma unroll 1
    for (int c = 0; c < 8; ++c) {
        if (c < 7) { load_b(c + 1, (c + 1) & 1); CP_COMMIT(); CP_WAIT1(); }
        else       { CP_WAIT0(); }
        __syncthreads();

        const unsigned bbuf = sb + OFF_B(c & 1) + bpart;

        float acc[8][4];
        #pragma unroll
        for (int nt = 0; nt < 8; ++nt)
            #pragma unroll
            for (int x = 0; x < 4; ++x) acc[nt][x] = 0.f;

        #pragma unroll
        for (int ks = 0; ks < 8; ++ks) {
            #pragma unroll
            for (int p = 0; p < 4; ++p) {      // pair p covers nt=2p, 2p+1
                unsigned b0, b1, b2, b3;
                LDSM_X4(b0, b1, b2, b3, bbuf + (unsigned)(p * 16) * SAB + ks * 32);
                mma_f16(acc[2 * p],     ahi[ks], b0, b1);
                mma_f16(acc[2 * p + 1], ahi[ks], b2, b3);
            }
        }

        const int colbase = c * 128 + half * 64 + (lane & 3) * 2;
        #pragma unroll
        for (int nt = 0; nt < 8; ++nt) {
            int nb = colbase + nt * 8;
            UPD(s1a, i1a, s2a, i2a, acc[nt][0], nb);
            UPD(s1a, i1a, s2a, i2a, acc[nt][1], nb + 1);
            UPD(s1b, i1b, s2b, i2b, acc[nt][2], nb);
            UPD(s1b, i1b, s2b, i2b, acc[nt][3], nb + 1);
        }
        __syncthreads();
    }

    // ---- quad merge -> (row, half) top-2 ----
    #pragma unroll
    for (int off = 1; off <= 2; off <<= 1) {
        float t1 = __shfl_xor_sync(0xffffffffu, s1a, off);
        int   j1 = __shfl_xor_sync(0xffffffffu, i1a, off);
        float t2 = __shfl_xor_sync(0xffffffffu, s2a, off);
        int   j2 = __shfl_xor_sync(0xffffffffu, i2a, off);
        merge2(s1a, i1a, s2a, i2a, t1, j1, t2, j2);
        t1 = __shfl_xor_sync(0xffffffffu, s1b, off);
        j1 = __shfl_xor_sync(0xffffffffu, i1b, off);
        t2 = __shfl_xor_sync(0xffffffffu, s2b, off);
        j2 = __shfl_xor_sync(0xffffffffu, i2b, off);
        merge2(s1b, i1b, s2b, i2b, t1, j1, t2, j2);
    }

    int* cand = (int*)smem;          // [128][4], 2KB, reuses A region
    if ((lane & 3) == 0) {
        int ra = rowg + (lane >> 2);
        cand[ra * 4 + half * 2 + 0]       = i1a;
        cand[ra * 4 + half * 2 + 1]       = i2a;
        cand[(ra + 8) * 4 + half * 2 + 0] = i1b;
        cand[(ra + 8) * 4 + half * 2 + 1] = i2b;
    }
    __syncthreads();

    // ---- epilogue: 4 threads/row. Exact fp32 rescore of 4 candidates, pick,
    //      then losses. Each thread owns a 32-elem quarter. ----
    {
        int row = tid >> 2;
        int sub = tid & 3;
        int grow = row0 + row;
        int4 cd = *(const int4*)&cand[row * 4];
        int cidx[4] = {cd.x, cd.y, cd.z, cd.w};

        const float4* qp = (const float4*)(q + (size_t)grow * C_DIM + sub * 32);
        float4 qv[8];
        #pragma unroll
        for (int i = 0; i < 8; ++i) qv[i] = qp[i];

        float dots[4];
        #pragma unroll
        for (int j = 0; j < 4; ++j) {
            const float4* kp = (const float4*)(keys + (size_t)cidx[j] * C_DIM + sub * 32);
            float s = 0.f;
            #pragma unroll
            for (int i = 0; i < 8; ++i) {
                float4 a = qv[i], b = kp[i];
                s = fmaf(a.x, b.x, s); s = fmaf(a.y, b.y, s);
                s = fmaf(a.z, b.z, s); s = fmaf(a.w, b.w, s);
            }
            dots[j] = s;
        }
        #pragma unroll
        for (int off = 1; off <= 2; off <<= 1)
            #pragma unroll
            for (int j = 0; j < 4; ++j)
                dots[j] += __shfl_xor_sync(0xffffffffu, dots[j], off);

        int   bi = cidx[0];
        float bs = dots[0];
        #pragma unroll
        for (int j = 1; j < 4; ++j)
            if (dots[j] > bs || (dots[j] == bs && cidx[j] < bi)) { bs = dots[j]; bi = cidx[j]; }

        const float4* kp = (const float4*)(keys   + (size_t)bi   * C_DIM + sub * 32);
        const float4* rp = (const float4*)(r      + (size_t)grow * C_DIM + sub * 32);
        const float4* vp = (const float4*)(values + (size_t)bi   * C_DIM + sub * 32);
        float sk = 0.f, sv = 0.f;
        #pragma unroll
        for (int i = 0; i < 8; ++i) {
            float4 a = qv[i], b = kp[i];
            float d;
            d = a.x - b.x; sk = fmaf(d, d, sk);
            d = a.y - b.y; sk = fmaf(d, d, sk);
            d = a.z - b.z; sk = fmaf(d, d, sk);
            d = a.w - b.w; sk = fmaf(d, d, sk);
            float4 e = rp[i], f = vp[i];
            d = e.x - f.x; sv = fmaf(d, d, sv);
            d = e.y - f.y; sv = fmaf(d, d, sv);
            d = e.z - f.z; sv = fmaf(d, d, sv);
            d = e.w - f.w; sv = fmaf(d, d, sv);
        }
        #pragma unroll
        for (int off = 1; off <= 2; off <<= 1) {
            sk += __shfl_xor_sync(0xffffffffu, sk, off);
            sv += __shfl_xor_sync(0xffffffffu, sv, off);
        }
        if (sub == 0) out[grow]           = sk;
        if (sub == 1) out[T_TOTAL + grow] = sv;
    }
}

extern "C" void kernel_launch(void* const* d_in, const int* in_sizes, int n_in,
                              void* d_out, int out_size)
{
    const float* q      = (const float*)d_in[0];
    const float* r      = (const float*)d_in[1];
    const float* keys   = (const float*)d_in[2];
    const float* values = (const float*)d_in[3];
    float* out = (float*)d_out;

    prep_keys_kernel<<<(M_KEYS * C_DIM + 255) / 256, 256>>>(keys);

    cudaFuncSetAttribute(gathering_loss_kernel,
                         cudaFuncAttributeMaxDynamicSharedMemorySize, SM_TOTAL);
    gathering_loss_kernel<<<T_TOTAL / BM, THREADS, SM_TOTAL>>>(q, r, keys, values, out);
}